// round 14
// baseline (speedup 1.0000x reference)
#include <cuda_runtime.h>
#include <math.h>

#define NM 1024
#define HH 256
#define WW 256
#define HW (HH * WW)
#define NBAND 4
#define BAND_F4 4096          // float4s per band (64 rows x 256 cols / 4)
#define GRID1 (NM * NBAND)    // 4096 CTAs of 128 threads
#define NZ 2048               // zero-fill chunks (256MB / 128KB)
#define ZCH_F4 8192           // float4s per zero chunk (128 threads x 64)

// Per-(mask,band) partials (every slot overwritten every launch)
__device__ int g_hiP[NM * NBAND];
__device__ int g_loP[NM * NBAND];
__device__ int g_minrP[NM * NBAND];
__device__ int g_maxrP[NM * NBAND];
__device__ int g_mincP[NM * NBAND];
__device__ int g_maxcP[NM * NBAND];

// NMS scratch + results
__device__ float4 g_box[NM];
__device__ float4 g_boxS[NM];
__device__ float g_areaS[NM];
__device__ float g_key[NM];
__device__ int g_vidx[NM];
__device__ int g_sorted[NM];
__device__ float2 g_kg[NM];    // {kept mask index as int bits, gate}
__device__ int g_nkept;

// Coordination. All counters return to 0 by end of each launch (reset by
// uniquely-identified last-ticket CTAs). NO CTA EVER SPIN-WAITS — safe at
// any occupancy / wave count.
__device__ unsigned g_done = 0;    // phase-A ticket (reset by NMS CTA)
__device__ unsigned g_zc = 0;      // zero chunk queue
__device__ unsigned g_done2 = 0;   // zero-phase ticket (last resets g_zc/g_done2)

__global__ __launch_bounds__(128)
void mega_k(const float* __restrict__ logits,
            float* __restrict__ out,
            const float* __restrict__ ioup,
            float* __restrict__ keep_out,
            float* __restrict__ boxes_out,
            int write_keep, int write_boxes) {
    const int tid = threadIdx.x;
    __shared__ int s[4][6];
    __shared__ int sIsNms, schunk;
    __shared__ int scnt, scnt2;
    __shared__ int skeep[NM];
    __shared__ int skeeporig[NM];

    // ============== Phase A: read-only band reduction (one band/CTA) =========
    {
        const int band = blockIdx.x & (NBAND - 1);
        const int n = blockIdx.x >> 2;
        const float4* p = reinterpret_cast<const float4*>(logits) +
                          (size_t)n * (HW / 4) + (size_t)band * BAND_F4;
        int hi = 0, lo = 0;
        unsigned rowmask = 0u;
        int colbits = 0;
#pragma unroll 8
        for (int it = 0; it < 32; ++it) {
            const float4 v = __ldcs(p + it * 128 + tid);
            hi += (v.x > 1.f) + (v.y > 1.f) + (v.z > 1.f) + (v.w > 1.f);
            lo += (v.x > -1.f) + (v.y > -1.f) + (v.z > -1.f) + (v.w > -1.f);
            const int b = (int)(v.x > 0.f) | ((int)(v.y > 0.f) << 1) |
                          ((int)(v.z > 0.f) << 2) | ((int)(v.w > 0.f) << 3);
            colbits |= b;
            rowmask |= (unsigned)(b != 0) << it;
        }
        int minr, maxr, minc, maxc;
        if (rowmask) {
            const int rowoff = (band << 6) + (tid >> 6);
            const int cbase = (tid & 63) << 2;
            minr = 2 * (__ffs(rowmask) - 1) + rowoff;
            maxr = 2 * (31 - __clz(rowmask)) + rowoff;
            minc = cbase + (__ffs(colbits) - 1);
            maxc = cbase + (31 - __clz((unsigned)colbits));
        } else {
            minr = HH; maxr = -1; minc = WW; maxc = -1;
        }
#pragma unroll
        for (int off = 16; off; off >>= 1) {
            hi += __shfl_down_sync(0xffffffffu, hi, off);
            lo += __shfl_down_sync(0xffffffffu, lo, off);
            minr = min(minr, __shfl_down_sync(0xffffffffu, minr, off));
            maxr = max(maxr, __shfl_down_sync(0xffffffffu, maxr, off));
            minc = min(minc, __shfl_down_sync(0xffffffffu, minc, off));
            maxc = max(maxc, __shfl_down_sync(0xffffffffu, maxc, off));
        }
        const int w = tid >> 5, l = tid & 31;
        if (l == 0) {
            s[w][0] = hi; s[w][1] = lo; s[w][2] = minr;
            s[w][3] = maxr; s[w][4] = minc; s[w][5] = maxc;
        }
        __syncthreads();
        if (tid == 0) {
            hi = s[0][0] + s[1][0] + s[2][0] + s[3][0];
            lo = s[0][1] + s[1][1] + s[2][1] + s[3][1];
            minr = min(min(s[0][2], s[1][2]), min(s[2][2], s[3][2]));
            maxr = max(max(s[0][3], s[1][3]), max(s[2][3], s[3][3]));
            minc = min(min(s[0][4], s[1][4]), min(s[2][4], s[3][4]));
            maxc = max(max(s[0][5], s[1][5]), max(s[2][5], s[3][5]));
            const int gi = (n << 2) + band;
            g_hiP[gi] = hi; g_loP[gi] = lo;
            g_minrP[gi] = minr; g_maxrP[gi] = maxr;
            g_mincP[gi] = minc; g_maxcP[gi] = maxc;
            __threadfence();                       // release partials
            const unsigned t = atomicAdd(&g_done, 1u);
            sIsNms = (t == (unsigned)(GRID1 - 1));
        }
        __syncthreads();
    }

    // ========= Last CTA: NMS (hidden behind other CTAs' zero-fill) =========
    if (sIsNms) {
        __threadfence();                           // acquire all partials
        if (tid == 0) { scnt = 0; scnt2 = 0; g_done = 0; }
        __syncthreads();
        for (int m = tid; m < NM; m += 128) {
            const int gi2 = m << 2;
            int h2 = 0, l2 = 0, mnr = HH, mxr = -1, mnc = WW, mxc = -1;
#pragma unroll
            for (int b = 0; b < NBAND; ++b) {
                h2 += g_hiP[gi2 + b];
                l2 += g_loP[gi2 + b];
                mnr = min(mnr, g_minrP[gi2 + b]);
                mxr = max(mxr, g_maxrP[gi2 + b]);
                mnc = min(mnc, g_mincP[gi2 + b]);
                mxc = max(mxc, g_maxcP[gi2 + b]);
            }
            const bool empty = (mxr < 0);
            const float4 bx = empty ? make_float4(0.f, 0.f, 0.f, 0.f)
                                    : make_float4((float)mnc, (float)mnr,
                                                  (float)mxc, (float)mxr);
            g_box[m] = bx;
            const float iou = ioup[m];
            g_key[m] = iou;
            skeeporig[m] = 0;
            const float stab = (float)h2 / fmaxf((float)l2, 1.0f);
            if ((iou > 0.88f) && (stab >= 0.95f)) {
                const int pp = atomicAdd(&scnt, 1);
                g_vidx[pp] = m;
            }
        }
        __syncthreads();
        const int V = scnt;
        // Rank sort (descending score, tie-break original index ascending)
        for (int v = tid; v < V; v += 128) {
            const int orig = g_vidx[v];
            const float key = g_key[orig];
            int rank = 0;
            for (int j = 0; j < V; ++j) {
                const int oj = g_vidx[j];
                const float kj = g_key[oj];
                rank += (int)((kj > key) | ((kj == key) & (oj < orig)));
            }
            g_sorted[rank] = orig;
        }
        __syncthreads();
        for (int v = tid; v < V; v += 128) {
            const float4 b = g_box[g_sorted[v]];
            g_boxS[v] = b;
            g_areaS[v] = fmaxf(b.z - b.x, 0.f) * fmaxf(b.w - b.y, 0.f);
            skeep[v] = 1;
        }
        __syncthreads();
        // Greedy suppression (head test uniform after loop-top barrier)
        for (int i = 0; i < V; ++i) {
            __syncthreads();
            if (!skeep[i]) continue;
            const float4 bi = g_boxS[i];
            const float area_i = g_areaS[i];
            for (int j = i + 1 + tid; j < V; j += 128) {
                if (skeep[j]) {
                    const float4 bj = g_boxS[j];
                    const float x0 = fmaxf(bi.x, bj.x);
                    const float y0 = fmaxf(bi.y, bj.y);
                    const float x1 = fminf(bi.z, bj.z);
                    const float y1 = fminf(bi.w, bj.w);
                    const float inter = fmaxf(x1 - x0, 0.f) * fmaxf(y1 - y0, 0.f);
                    const float u = fmaxf(area_i + g_areaS[j] - inter, 1e-6f);
                    if (inter > 0.7f * u) skeep[j] = 0;
                }
            }
        }
        __syncthreads();
        for (int v = tid; v < V; v += 128) {
            if (skeep[v]) {
                const int orig = g_sorted[v];
                skeeporig[orig] = 1;
                const int pp = atomicAdd(&scnt2, 1);
                g_kg[pp] = make_float2(__int_as_float(orig), g_key[orig]);
            }
        }
        __syncthreads();
        for (int m = tid; m < NM; m += 128) {
            const int kept = skeeporig[m];
            if (write_keep) keep_out[m] = kept ? 1.f : 0.f;
            if (write_boxes) reinterpret_cast<float4*>(boxes_out)[m] = g_box[m];
        }
        if (tid == 0) g_nkept = scnt2;
        __threadfence();                           // release NMS results
    }

    // ======== Zero-fill work-steal queue (concurrent with NMS) ========
    // Queue-based: CTAs launched late (multi-wave) simply grab fewer
    // chunks. No CTA waits on any other CTA.
    {
        const float4 z = make_float4(0.f, 0.f, 0.f, 0.f);
        float4* ob = reinterpret_cast<float4*>(out);
        for (;;) {
            if (tid == 0) schunk = (int)atomicAdd(&g_zc, 1u);
            __syncthreads();
            const int c = schunk;
            __syncthreads();
            if (c >= NZ) break;
            float4* o = ob + (size_t)c * ZCH_F4;
#pragma unroll 8
            for (int it = 0; it < 64; ++it) __stcs(o + it * 128 + tid, z);
        }
    }
    __threadfence();
    if (tid == 0) {
        const unsigned t2 = atomicAdd(&g_done2, 1u);
        if (t2 == (unsigned)(GRID1 - 1)) { g_zc = 0; g_done2 = 0; }
    }
}

// ---------------------------------------------------------------------------
// Kernel 2: sigmoid overwrite of kept masks (~26 of 1024). Fine 4KB chunks
// (256 float4, one per thread) to maximize concurrent MLP and minimize the
// latency tail. Non-kept masks already zeroed by kernel 1.
// ---------------------------------------------------------------------------
__global__ __launch_bounds__(256) void out_k(const float* __restrict__ logits,
                                             float* __restrict__ out) {
    const int total = g_nkept << 6;      // 64 chunks of 256 float4 per mask
    const int tid = threadIdx.x;
    for (int c = blockIdx.x; c < total; c += gridDim.x) {
        const float2 kg = g_kg[c >> 6];
        const int m = __float_as_int(kg.x);
        const float g = kg.y;
        const size_t base4 = (size_t)m * (HW / 4) + (size_t)(c & 63) * 256;
        const float4 v = __ldcs(reinterpret_cast<const float4*>(logits) + base4 + tid);
        float4 r;
        r.x = g * (1.f / (1.f + __expf(-v.x)));
        r.y = g * (1.f / (1.f + __expf(-v.y)));
        r.z = g * (1.f / (1.f + __expf(-v.z)));
        r.w = g * (1.f / (1.f + __expf(-v.w)));
        __stcs(reinterpret_cast<float4*>(out) + base4 + tid, r);
    }
}

extern "C" void kernel_launch(void* const* d_in, const int* in_sizes, int n_in,
                              void* d_out, int out_size) {
    const float* logits;
    const float* ioup;
    if (in_sizes[0] == NM) {
        ioup = (const float*)d_in[0];
        logits = (const float*)d_in[1];
    } else {
        logits = (const float*)d_in[0];
        ioup = (const float*)d_in[1];
    }

    float* out = (float*)d_out;
    const long long main_sz = (long long)NM * HW;
    const int wk = ((long long)out_size >= main_sz + NM) ? 1 : 0;
    const int wb = ((long long)out_size >= main_sz + NM + 4LL * NM) ? 1 : 0;
    float* keep_out = out + (size_t)NM * HW;
    float* boxes_out = keep_out + NM;

    mega_k<<<GRID1, 128>>>(logits, out, ioup, keep_out, boxes_out, wk, wb);
    out_k<<<2048, 256>>>(logits, out);
}

// round 15
// speedup vs baseline: 1.0122x; 1.0122x over previous
#include <cuda_runtime.h>
#include <math.h>

#define NM 1024
#define HH 256
#define WW 256
#define HW (HH * WW)
#define NBAND 4
#define BAND_F4 4096          // float4s per band
#define GRID1 (NM * NBAND)    // 4096 CTAs x 128 threads
#define IT_INL 26             // iterations zero-filled inline (of 32)
#define CAP 320               // shared-path capacity for valid masks
#define MAXCH (NM * 64)       // max output chunks (4KB each)

// Packed per-(mask,band) partials: x=hi<<16|lo, y=minr<<16|minc, z=(maxr+1)<<16|(maxc+1)
__device__ int4 g_part[NM * NBAND];
__device__ float4 g_box[NM];

// NMS fallback mirrors (used only if V > CAP)
__device__ float g_ckeyG[NM];
__device__ int   g_cidxG[NM];
__device__ int   g_csortG[NM];
__device__ int   g_ckeepG[NM];
__device__ float4 g_cboxG[NM];
__device__ float g_careaG[NM];

// Output-chunk descriptors for out_k: {mask index as int bits, gate}
__device__ float2 g_cd[MAXCH];
__device__ int g_ntot;

// Coordination: every counter returns to 0 each launch via uniquely-identified
// last-ticket CTAs. NO CTA EVER SPIN-WAITS (safe at any occupancy/waves).
__device__ unsigned g_done = 0;    // reduce ticket (reset by NMS CTA)
__device__ unsigned g_zq = 0;      // deferred-zero chunk queue
__device__ unsigned g_done2 = 0;   // end ticket (last resets g_zq/g_done2)

__global__ __launch_bounds__(128)
void mega_k(const float* __restrict__ logits,
            float* __restrict__ out,
            const float* __restrict__ ioup,
            float* __restrict__ keep_out,
            float* __restrict__ boxes_out,
            int write_keep, int write_boxes) {
    const int tid = threadIdx.x;
    __shared__ int s[4][6];
    __shared__ int sIsNms, schunk;
    __shared__ int scnt, scnt2;
    // NMS shared scratch (compacted, CAP slots). ~11.5KB: keeps 16 CTAs/SM.
    __shared__ float shkey[CAP];
    __shared__ int   shidx[CAP];
    __shared__ int   shsort[CAP];
    __shared__ int   shkeep[CAP];
    __shared__ float4 shbox[CAP];
    __shared__ float sharea[CAP];

    // ======== Phase A: fused read + reduce + inline zero (26/32 iters) ========
    {
        const int band = blockIdx.x & (NBAND - 1);
        const int n = blockIdx.x >> 2;
        const size_t base4 = (size_t)n * (HW / 4) + (size_t)band * BAND_F4;
        const float4* p = reinterpret_cast<const float4*>(logits) + base4;
        float4* o = reinterpret_cast<float4*>(out) + base4;
        const float4 z = make_float4(0.f, 0.f, 0.f, 0.f);

        int hi = 0, lo = 0;
        unsigned rowmask = 0u;
        int colbits = 0;
#pragma unroll 2
        for (int it = 0; it < IT_INL; ++it) {
            const float4 v = __ldcs(p + it * 128 + tid);
            __stcs(o + it * 128 + tid, z);
            hi += (v.x > 1.f) + (v.y > 1.f) + (v.z > 1.f) + (v.w > 1.f);
            lo += (v.x > -1.f) + (v.y > -1.f) + (v.z > -1.f) + (v.w > -1.f);
            const int b = (int)(v.x > 0.f) | ((int)(v.y > 0.f) << 1) |
                          ((int)(v.z > 0.f) << 2) | ((int)(v.w > 0.f) << 3);
            colbits |= b;
            rowmask |= (unsigned)(b != 0) << it;
        }
#pragma unroll
        for (int it = IT_INL; it < 32; ++it) {    // reads only; zeros deferred
            const float4 v = __ldcs(p + it * 128 + tid);
            hi += (v.x > 1.f) + (v.y > 1.f) + (v.z > 1.f) + (v.w > 1.f);
            lo += (v.x > -1.f) + (v.y > -1.f) + (v.z > -1.f) + (v.w > -1.f);
            const int b = (int)(v.x > 0.f) | ((int)(v.y > 0.f) << 1) |
                          ((int)(v.z > 0.f) << 2) | ((int)(v.w > 0.f) << 3);
            colbits |= b;
            rowmask |= (unsigned)(b != 0) << it;
        }

        int minr, maxr, minc, maxc;
        if (rowmask) {
            const int rowoff = (band << 6) + (tid >> 6);
            const int cbase = (tid & 63) << 2;
            minr = 2 * (__ffs(rowmask) - 1) + rowoff;
            maxr = 2 * (31 - __clz(rowmask)) + rowoff;
            minc = cbase + (__ffs(colbits) - 1);
            maxc = cbase + (31 - __clz((unsigned)colbits));
        } else {
            minr = HH; maxr = -1; minc = WW; maxc = -1;
        }
#pragma unroll
        for (int off = 16; off; off >>= 1) {
            hi += __shfl_down_sync(0xffffffffu, hi, off);
            lo += __shfl_down_sync(0xffffffffu, lo, off);
            minr = min(minr, __shfl_down_sync(0xffffffffu, minr, off));
            maxr = max(maxr, __shfl_down_sync(0xffffffffu, maxr, off));
            minc = min(minc, __shfl_down_sync(0xffffffffu, minc, off));
            maxc = max(maxc, __shfl_down_sync(0xffffffffu, maxc, off));
        }
        const int w = tid >> 5, l = tid & 31;
        if (l == 0) {
            s[w][0] = hi; s[w][1] = lo; s[w][2] = minr;
            s[w][3] = maxr; s[w][4] = minc; s[w][5] = maxc;
        }
        __syncthreads();
        if (tid == 0) {
            hi = s[0][0] + s[1][0] + s[2][0] + s[3][0];
            lo = s[0][1] + s[1][1] + s[2][1] + s[3][1];
            minr = min(min(s[0][2], s[1][2]), min(s[2][2], s[3][2]));
            maxr = max(max(s[0][3], s[1][3]), max(s[2][3], s[3][3]));
            minc = min(min(s[0][4], s[1][4]), min(s[2][4], s[3][4]));
            maxc = max(max(s[0][5], s[1][5]), max(s[2][5], s[3][5]));
            int4 pk;
            pk.x = (hi << 16) | lo;
            pk.y = (minr << 16) | minc;
            pk.z = ((maxr + 1) << 16) | (maxc + 1);
            pk.w = 0;
            g_part[(n << 2) + band] = pk;
            __threadfence();
            const unsigned t = atomicAdd(&g_done, 1u);
            sIsNms = (t == (unsigned)(GRID1 - 1));
        }
        __syncthreads();
    }

    // ===== Last CTA: NMS (hidden behind other CTAs' deferred zero-fill) =====
    if (sIsNms) {
        __threadfence();
        if (tid == 0) { scnt = 0; scnt2 = 0; g_done = 0; }
        __syncthreads();
        // Combine partials; validity; compaction (shared + global mirror)
        for (int m = tid; m < NM; m += 128) {
            const int gi = m << 2;
            int h2 = 0, l2 = 0, mnr = HH, mxr = -1, mnc = WW, mxc = -1;
#pragma unroll
            for (int b = 0; b < NBAND; ++b) {
                const int4 pk = g_part[gi + b];
                h2 += pk.x >> 16;
                l2 += pk.x & 0xffff;
                mnr = min(mnr, pk.y >> 16);
                mnc = min(mnc, pk.y & 0xffff);
                mxr = max(mxr, (pk.z >> 16) - 1);
                mxc = max(mxc, (pk.z & 0xffff) - 1);
            }
            const bool empty = (mxr < 0);
            const float4 bx = empty ? make_float4(0.f, 0.f, 0.f, 0.f)
                                    : make_float4((float)mnc, (float)mnr,
                                                  (float)mxc, (float)mxr);
            g_box[m] = bx;
            if (write_keep) keep_out[m] = 0.f;
            if (write_boxes) reinterpret_cast<float4*>(boxes_out)[m] = bx;
            const float iou = ioup[m];
            const float stab = (float)h2 / fmaxf((float)l2, 1.0f);
            if ((iou > 0.88f) && (stab >= 0.95f)) {
                const int pp = atomicAdd(&scnt, 1);
                g_cidxG[pp] = m;
                g_ckeyG[pp] = iou;
                if (pp < CAP) { shidx[pp] = m; shkey[pp] = iou; }
            }
        }
        __syncthreads();
        const int V = scnt;
        const bool useSh = (V <= CAP);
        float* ckey = useSh ? shkey : g_ckeyG;
        int*   cidx = useSh ? shidx : g_cidxG;
        int*   csort = useSh ? shsort : g_csortG;
        int*   ckeep = useSh ? shkeep : g_ckeepG;
        float4* cbox = useSh ? shbox : g_cboxG;
        float* carea = useSh ? sharea : g_careaG;

        // Rank sort (descending key, tie-break original index ascending)
        for (int v = tid; v < V; v += 128) {
            const float key = ckey[v];
            const int orig = cidx[v];
            int rank = 0;
            for (int j = 0; j < V; ++j) {
                const float kj = ckey[j];
                const int oj = cidx[j];
                rank += (int)((kj > key) | ((kj == key) & (oj < orig)));
            }
            csort[rank] = orig;
        }
        __syncthreads();
        for (int v = tid; v < V; v += 128) {
            const float4 b = g_box[csort[v]];
            cbox[v] = b;
            carea[v] = fmaxf(b.z - b.x, 0.f) * fmaxf(b.w - b.y, 0.f);
            ckeep[v] = 1;
        }
        __syncthreads();
        // Greedy suppression (head test uniform after loop-top barrier)
        for (int i = 0; i < V; ++i) {
            __syncthreads();
            if (!ckeep[i]) continue;
            const float4 bi = cbox[i];
            const float area_i = carea[i];
            for (int j = i + 1 + tid; j < V; j += 128) {
                if (ckeep[j]) {
                    const float4 bj = cbox[j];
                    const float x0 = fmaxf(bi.x, bj.x);
                    const float y0 = fmaxf(bi.y, bj.y);
                    const float x1 = fminf(bi.z, bj.z);
                    const float y1 = fminf(bi.w, bj.w);
                    const float inter = fmaxf(x1 - x0, 0.f) * fmaxf(y1 - y0, 0.f);
                    const float u = fmaxf(area_i + carea[j] - inter, 1e-6f);
                    if (inter > 0.7f * u) ckeep[j] = 0;
                }
            }
        }
        __syncthreads();
        // Kept set -> reuse ckey/cidx as {gate, mask} compaction
        for (int v = tid; v < V; v += 128) {
            if (ckeep[v]) {
                const int orig = csort[v];
                const float gate = ioup[orig];
                if (write_keep) keep_out[orig] = 1.f;
                const int kk = atomicAdd(&scnt2, 1);
                cidx[kk] = orig;
                ckey[kk] = gate;
            }
        }
        __syncthreads();
        const int nk = scnt2;
        // Dense chunk descriptors for out_k (64 x 4KB chunks per kept mask)
        for (int c = tid; c < (nk << 6); c += 128) {
            const int kk = c >> 6;
            g_cd[c] = make_float2(__int_as_float(cidx[kk]), ckey[kk]);
        }
        if (tid == 0) g_ntot = nk << 6;
        __threadfence();
    }

    // ===== Deferred zero-fill queue (runs concurrently with NMS) =====
    {
        const float4 z = make_float4(0.f, 0.f, 0.f, 0.f);
        float4* ob = reinterpret_cast<float4*>(out);
        for (;;) {
            if (tid == 0) schunk = (int)atomicAdd(&g_zq, 1u);
            __syncthreads();
            const int c = schunk;
            __syncthreads();
            if (c >= GRID1) break;
            float4* o = ob + (size_t)(c >> 2) * (HW / 4) + (size_t)(c & 3) * BAND_F4;
#pragma unroll
            for (int it = IT_INL; it < 32; ++it)
                __stcs(o + it * 128 + tid, z);
        }
    }
    __threadfence();
    if (tid == 0) {
        const unsigned t2 = atomicAdd(&g_done2, 1u);
        if (t2 == (unsigned)(GRID1 - 1)) { g_zq = 0; g_done2 = 0; }
    }
}

// ---------------------------------------------------------------------------
// Kernel 2: sigmoid overwrite of kept masks via precomputed descriptors.
// 4KB chunks (256 threads x 1 float4): minimal dependency chain per block.
// ---------------------------------------------------------------------------
__global__ __launch_bounds__(256) void out_k(const float* __restrict__ logits,
                                             float* __restrict__ out) {
    const int total = g_ntot;
    const int tid = threadIdx.x;
    for (int c = blockIdx.x; c < total; c += gridDim.x) {
        const float2 kg = g_cd[c];
        const int m = __float_as_int(kg.x);
        const float g = kg.y;
        const size_t base4 = (size_t)m * (HW / 4) + (size_t)(c & 63) * 256;
        const float4 v = __ldcs(reinterpret_cast<const float4*>(logits) + base4 + tid);
        float4 r;
        r.x = g * (1.f / (1.f + __expf(-v.x)));
        r.y = g * (1.f / (1.f + __expf(-v.y)));
        r.z = g * (1.f / (1.f + __expf(-v.z)));
        r.w = g * (1.f / (1.f + __expf(-v.w)));
        __stcs(reinterpret_cast<float4*>(out) + base4 + tid, r);
    }
}

extern "C" void kernel_launch(void* const* d_in, const int* in_sizes, int n_in,
                              void* d_out, int out_size) {
    const float* logits;
    const float* ioup;
    if (in_sizes[0] == NM) {
        ioup = (const float*)d_in[0];
        logits = (const float*)d_in[1];
    } else {
        logits = (const float*)d_in[0];
        ioup = (const float*)d_in[1];
    }

    float* out = (float*)d_out;
    const long long main_sz = (long long)NM * HW;
    const int wk = ((long long)out_size >= main_sz + NM) ? 1 : 0;
    const int wb = ((long long)out_size >= main_sz + NM + 4LL * NM) ? 1 : 0;
    float* keep_out = out + (size_t)NM * HW;
    float* boxes_out = keep_out + NM;

    mega_k<<<GRID1, 128>>>(logits, out, ioup, keep_out, boxes_out, wk, wb);
    out_k<<<2048, 256>>>(logits, out);
}